// round 15
// baseline (speedup 1.0000x reference)
#include <cuda_runtime.h>
#include <math.h>

#define D 690
#define R 53
#define NU 11            // 345 float2 per row = 10 full warp-strides + 25-lane tail
#define NBMAX 25000
#define NSPLIT 4
typedef unsigned long long ull;

__device__ float g_att[NBMAX * D];            // 69 MB scratch (L2-pinned via evict_last)
__device__ float g_part[NSPLIT * NBMAX * R];  // 21 MB split-K partials

#define FFMA2(d, a, b)   asm("fma.rn.f32x2 %0, %1, %2, %0;" : "+l"(d) : "l"(a), "l"(b))
#define MUL2(d, a, b)    asm("mul.rn.f32x2 %0, %1, %2;"     : "=l"(d) : "l"(a), "l"(b))
#define PACK2(d, x)      asm("mov.b64 %0, {%1, %1};"        : "=l"(d) : "f"(x))

#define LDG_EF(dst, ptr, pol) \
    asm("ld.global.nc.L2::cache_hint.b64 %0, [%1], %2;" \
        : "=l"(dst) : "l"(ptr), "l"(pol))
#define STG_EL(ptr, val, pol) \
    asm volatile("st.global.L2::cache_hint.b64 [%0], %1, %2;" \
                 :: "l"(ptr), "l"(val), "l"(pol) : "memory")

__device__ __forceinline__ float h2sum(ull v) {
    float a, b;
    asm("mov.b64 {%0, %1}, %2;" : "=f"(a), "=f"(b) : "l"(v));
    return a + b;
}

// ---------------------------------------------------------------------------
// Kernel 1 (frozen R14): one 32-thread CTA per bag, single pass, online exp
// (shift-invariant softmax, no max), ping-pong prefetch, L2 residency hints.
// ---------------------------------------------------------------------------
__global__ __launch_bounds__(32)
void bag_att_kernel(const float* __restrict__ repre,
                    const float* __restrict__ rel,
                    const int* __restrict__ scope,
                    const int* __restrict__ labels,
                    float* __restrict__ att_out)
{
    const int bag  = blockIdx.x;
    const int lane = threadIdx.x;
    const bool tail = lane < 25;                  // 345 = 10*32 + 25

    const int start = scope[2 * bag];
    const int end   = scope[2 * bag + 1];

    ull pol_ef, pol_el;
    asm("createpolicy.fractional.L2::evict_first.b64 %0, 1.0;" : "=l"(pol_ef));
    asm("createpolicy.fractional.L2::evict_last.b64 %0, 1.0;"  : "=l"(pol_el));

    float s = 0.f;
    ull acc[NU];
    #pragma unroll
    for (int u = 0; u < NU; ++u) acc[u] = 0ull;

    ull bufA[NU], bufB[NU];
    int labA, labB;

    #define LOADROW(buf, lab, r)                                            \
        do {                                                                \
            const ull* rp2 = (const ull*)(repre + (size_t)(r) * D);         \
            lab = labels[r];                                                \
            _Pragma("unroll")                                               \
            for (int u = 0; u < 10; ++u)                                    \
                LDG_EF(buf[u], rp2 + lane + 32 * u, pol_ef);                \
            if (tail) LDG_EF(buf[10], rp2 + lane + 320, pol_ef);            \
            else buf[10] = 0ull;                                            \
        } while (0)

    #define PROCROW(buf, lab)                                               \
        do {                                                                \
            const ull* rv2 = (const ull*)(rel + (size_t)(lab) * D);         \
            ull d2a = 0ull, d2b = 0ull;                                     \
            _Pragma("unroll")                                               \
            for (int u = 0; u < 10; u += 2) {                               \
                ull v0 = rv2[lane + 32 * u];                                \
                ull v1 = rv2[lane + 32 * (u + 1)];                          \
                FFMA2(d2a, buf[u], v0);                                     \
                FFMA2(d2b, buf[u + 1], v1);                                 \
            }                                                               \
            if (tail) {                                                     \
                ull v = rv2[lane + 320];                                    \
                FFMA2(d2a, buf[10], v);                                     \
            }                                                               \
            float dot = h2sum(d2a) + h2sum(d2b);                            \
            _Pragma("unroll")                                               \
            for (int o = 16; o; o >>= 1)                                    \
                dot += __shfl_xor_sync(0xffffffffu, dot, o);                \
            const float e = __expf(dot);                                    \
            s += e;                                                         \
            ull e2;                                                         \
            PACK2(e2, e);                                                   \
            _Pragma("unroll")                                               \
            for (int u = 0; u < NU; ++u)                                    \
                FFMA2(acc[u], e2, buf[u]);                                  \
        } while (0)

    {
        int r = start;
        LOADROW(bufA, labA, r);
        for (;;) {
            const int r1 = r + 1;
            const bool hb = r1 < end;
            if (hb) LOADROW(bufB, labB, r1);
            PROCROW(bufA, labA);
            if (!hb) break;
            const int r2 = r + 2;
            const bool ha = r2 < end;
            if (ha) LOADROW(bufA, labA, r2);
            PROCROW(bufB, labB);
            if (!ha) break;
            r = r2;
        }
    }

    ull invS2;
    PACK2(invS2, 1.f / s);
    ull* dst = (ull*)(att_out + (size_t)bag * D);
    #pragma unroll
    for (int u = 0; u < 10; ++u) {
        ull t;
        MUL2(t, acc[u], invS2);
        STG_EL(dst + lane + 32 * u, t, pol_el);
    }
    if (tail) {
        ull t;
        MUL2(t, acc[10], invS2);
        STG_EL(dst + lane + 320, t, pol_el);
    }
}

// ---------------------------------------------------------------------------
// Kernel 2: SPLIT-K GEMM. blockIdx.x = bag tile (64 bags), blockIdx.y = split.
// Each split handles 11 of the 44 k-chunks -> 4x the CTAs in flight,
// 1/4 the serial chain per CTA. Partials to g_part (no atomics).
// ---------------------------------------------------------------------------
#define BK 16
#define CHUNKS_PER_SPLIT 11   // 44 total chunks / 4 splits
#define TST 68                // smem row stride (floats), %4==0 for LDS.128

__global__ __launch_bounds__(128)
void bag_logits_gemm(const float* __restrict__ att,
                     const float* __restrict__ rel,
                     float* __restrict__ part,
                     int num_bags)
{
    __shared__ __align__(16) float As[BK][TST];
    __shared__ __align__(16) float Bs[BK][TST];

    const int tid  = threadIdx.x;
    const int m0   = (tid & 15) * 4;        // 4 consecutive bags per thread
    const int n0   = (tid >> 4) * 8;        // 8 consecutive n per thread
    const int bRow = blockIdx.x * 64;
    const int spl  = blockIdx.y;
    const int cBase = spl * CHUNKS_PER_SPLIT;

    const int lc = tid & 15;                // k within chunk
    const int lr = tid >> 4;                // row base (stride 8)

    ull acc[4][4];
    #pragma unroll
    for (int i = 0; i < 4; ++i)
        #pragma unroll
        for (int j = 0; j < 4; ++j) acc[i][j] = 0ull;

    float aReg[8], bReg[8];

    #define LOADTILE(k0)                                                     \
        do {                                                                 \
            _Pragma("unroll")                                                \
            for (int p = 0; p < 8; ++p) {                                    \
                int r = lr + p * 8;                                          \
                int bag = bRow + r, k = (k0) + lc;                           \
                aReg[p] = (bag < num_bags && k < D)                          \
                              ? att[(size_t)bag * D + k] : 0.f;              \
                bReg[p] = (r < R && k < D)                                   \
                              ? rel[(size_t)r * D + k] : 0.f;                \
            }                                                                \
        } while (0)

    LOADTILE(cBase * BK);

    for (int t = 0; t < CHUNKS_PER_SPLIT; ++t) {
        #pragma unroll
        for (int p = 0; p < 8; ++p) {
            As[lc][lr + p * 8] = aReg[p];
            Bs[lc][lr + p * 8] = bReg[p];
        }
        __syncthreads();

        if (t + 1 < CHUNKS_PER_SPLIT) LOADTILE((cBase + t + 1) * BK);

        #pragma unroll
        for (int kk = 0; kk < BK; ++kk) {
            float4 av = *(const float4*)&As[kk][m0];
            ull a0d, a1d, a2d, a3d;
            PACK2(a0d, av.x);
            PACK2(a1d, av.y);
            PACK2(a2d, av.z);
            PACK2(a3d, av.w);
            const ull* bp = (const ull*)&Bs[kk][n0];
            ull b01 = bp[0], b23 = bp[1], b45 = bp[2], b67 = bp[3];
            FFMA2(acc[0][0], a0d, b01); FFMA2(acc[0][1], a0d, b23);
            FFMA2(acc[0][2], a0d, b45); FFMA2(acc[0][3], a0d, b67);
            FFMA2(acc[1][0], a1d, b01); FFMA2(acc[1][1], a1d, b23);
            FFMA2(acc[1][2], a1d, b45); FFMA2(acc[1][3], a1d, b67);
            FFMA2(acc[2][0], a2d, b01); FFMA2(acc[2][1], a2d, b23);
            FFMA2(acc[2][2], a2d, b45); FFMA2(acc[2][3], a2d, b67);
            FFMA2(acc[3][0], a3d, b01); FFMA2(acc[3][1], a3d, b23);
            FFMA2(acc[3][2], a3d, b45); FFMA2(acc[3][3], a3d, b67);
        }
        __syncthreads();
    }

    // store partials (no bias here)
    float* pbase = part + (size_t)spl * num_bags * R;
    #pragma unroll
    for (int mm = 0; mm < 4; ++mm) {
        int bag = bRow + m0 + mm;
        if (bag >= num_bags) continue;
        #pragma unroll
        for (int j = 0; j < 4; ++j) {
            union { ull u; float2 f; } v;
            v.u = acc[mm][j];
            int n = n0 + 2 * j;
            if (n < R)     pbase[(size_t)bag * R + n]     = v.f.x;
            if (n + 1 < R) pbase[(size_t)bag * R + n + 1] = v.f.y;
        }
    }
}

// ---------------------------------------------------------------------------
// Kernel 3: reduce the 4 split partials + bias.
// ---------------------------------------------------------------------------
__global__ __launch_bounds__(256)
void reduce_kernel(const float* __restrict__ part,
                   const float* __restrict__ bias,
                   float* __restrict__ out,
                   int total)               // total = num_bags * R
{
    int i = blockIdx.x * 256 + threadIdx.x;
    if (i >= total) return;
    float v = part[i];
    #pragma unroll
    for (int s = 1; s < NSPLIT; ++s)
        v += part[(size_t)s * total + i];
    out[i] = v + bias[i % R];
}

extern "C" void kernel_launch(void* const* d_in, const int* in_sizes, int n_in,
                              void* d_out, int out_size)
{
    const float* repre  = (const float*)d_in[0];
    const float* rel    = (const float*)d_in[1];
    const float* bias   = (const float*)d_in[2];
    const int*   scope  = (const int*)d_in[3];
    const int*   labels = (const int*)d_in[4];
    float* out = (float*)d_out;

    const int num_bags = in_sizes[3] / 2;

    float *att, *part;
    cudaGetSymbolAddress((void**)&att, g_att);
    cudaGetSymbolAddress((void**)&part, g_part);

    bag_att_kernel<<<num_bags, 32>>>(repre, rel, scope, labels, att);

    dim3 grid2((num_bags + 63) / 64, NSPLIT);
    bag_logits_gemm<<<grid2, 128>>>(att, rel, part, num_bags);

    int total = num_bags * R;
    reduce_kernel<<<(total + 255) / 256, 256>>>(part, bias, out, total);
}

// round 16
// speedup vs baseline: 1.4240x; 1.4240x over previous
#include <cuda_runtime.h>
#include <math.h>

#define D 690
#define R 53
#define NU 11            // 345 float2 per row = 10 full warp-strides + 25-lane tail
typedef unsigned long long ull;

__device__ float g_att[25000 * D];   // 69 MB scratch (L2-pinned via evict_last)

#define FFMA2(d, a, b)   asm("fma.rn.f32x2 %0, %1, %2, %0;" : "+l"(d) : "l"(a), "l"(b))
#define MUL2(d, a, b)    asm("mul.rn.f32x2 %0, %1, %2;"     : "=l"(d) : "l"(a), "l"(b))
#define PACK2(d, x)      asm("mov.b64 %0, {%1, %1};"        : "=l"(d) : "f"(x))

#define LDG_EF(dst, ptr, pol) \
    asm("ld.global.nc.L2::cache_hint.b64 %0, [%1], %2;" \
        : "=l"(dst) : "l"(ptr), "l"(pol))
#define STG_EL(ptr, val, pol) \
    asm volatile("st.global.L2::cache_hint.b64 [%0], %1, %2;" \
                 :: "l"(ptr), "l"(val), "l"(pol) : "memory")

__device__ __forceinline__ float h2sum(ull v) {
    float a, b;
    asm("mov.b64 {%0, %1}, %2;" : "=f"(a), "=f"(b) : "l"(v));
    return a + b;
}

// ---------------------------------------------------------------------------
// Kernel 1: one 32-thread CTA per bag, single pass over repre.
// PAIR-PROCESSED online exp accumulation (rows are order-independent since
// no max subtraction): 2 rows in flight -> interleaved dot chains and
// interleaved shfl reductions halve the exposed serial latency per row.
// Ping-pong at pair granularity. L2 hints: repre evict_first, att evict_last.
// ---------------------------------------------------------------------------
__global__ __launch_bounds__(32)
void bag_att_kernel(const float* __restrict__ repre,
                    const float* __restrict__ rel,
                    const int* __restrict__ scope,
                    const int* __restrict__ labels,
                    float* __restrict__ att_out)
{
    const int bag  = blockIdx.x;
    const int lane = threadIdx.x;
    const bool tail = lane < 25;                  // 345 = 10*32 + 25

    const int start = scope[2 * bag];
    const int end   = scope[2 * bag + 1];

    ull pol_ef, pol_el;
    asm("createpolicy.fractional.L2::evict_first.b64 %0, 1.0;" : "=l"(pol_ef));
    asm("createpolicy.fractional.L2::evict_last.b64 %0, 1.0;"  : "=l"(pol_el));

    float s = 0.f;
    ull acc[NU];
    #pragma unroll
    for (int u = 0; u < NU; ++u) acc[u] = 0ull;

    ull a0[NU], a1[NU], b0[NU], b1[NU];
    int la0, la1, lb0, lb1;

    #define LOADROW(buf, lab, r)                                            \
        do {                                                                \
            const ull* rp2 = (const ull*)(repre + (size_t)(r) * D);         \
            lab = labels[r];                                                \
            _Pragma("unroll")                                               \
            for (int u = 0; u < 10; ++u)                                    \
                LDG_EF(buf[u], rp2 + lane + 32 * u, pol_ef);                \
            if (tail) LDG_EF(buf[10], rp2 + lane + 320, pol_ef);            \
            else buf[10] = 0ull;                                            \
        } while (0)

    // single-row update (for odd leading row)
    #define PROCROW(buf, lab)                                               \
        do {                                                                \
            const ull* rv2 = (const ull*)(rel + (size_t)(lab) * D);         \
            ull d2a = 0ull, d2b = 0ull;                                     \
            _Pragma("unroll")                                               \
            for (int u = 0; u < 10; u += 2) {                               \
                ull v0 = rv2[lane + 32 * u];                                \
                ull v1 = rv2[lane + 32 * (u + 1)];                          \
                FFMA2(d2a, buf[u], v0);                                     \
                FFMA2(d2b, buf[u + 1], v1);                                 \
            }                                                               \
            if (tail) {                                                     \
                ull v = rv2[lane + 320];                                    \
                FFMA2(d2a, buf[10], v);                                     \
            }                                                               \
            float dot = h2sum(d2a) + h2sum(d2b);                            \
            _Pragma("unroll")                                               \
            for (int o = 16; o; o >>= 1)                                    \
                dot += __shfl_xor_sync(0xffffffffu, dot, o);                \
            const float e = __expf(dot);                                    \
            s += e;                                                         \
            ull e2;                                                         \
            PACK2(e2, e);                                                   \
            _Pragma("unroll")                                               \
            for (int u = 0; u < NU; ++u)                                    \
                FFMA2(acc[u], e2, buf[u]);                                  \
        } while (0)

    // two rows concurrently: 4 independent dot chains, interleaved shfls
    #define PROCPAIR(p0, l0, p1, l1)                                        \
        do {                                                                \
            const ull* rv0 = (const ull*)(rel + (size_t)(l0) * D);          \
            const ull* rv1 = (const ull*)(rel + (size_t)(l1) * D);          \
            ull d0a = 0ull, d0b = 0ull, d1a = 0ull, d1b = 0ull;             \
            _Pragma("unroll")                                               \
            for (int u = 0; u < 10; u += 2) {                               \
                ull w0 = rv0[lane + 32 * u];                                \
                ull w1 = rv0[lane + 32 * (u + 1)];                          \
                ull x0 = rv1[lane + 32 * u];                                \
                ull x1 = rv1[lane + 32 * (u + 1)];                          \
                FFMA2(d0a, p0[u], w0);                                      \
                FFMA2(d1a, p1[u], x0);                                      \
                FFMA2(d0b, p0[u + 1], w1);                                  \
                FFMA2(d1b, p1[u + 1], x1);                                  \
            }                                                               \
            if (tail) {                                                     \
                ull w = rv0[lane + 320];                                    \
                ull x = rv1[lane + 320];                                    \
                FFMA2(d0a, p0[10], w);                                      \
                FFMA2(d1a, p1[10], x);                                      \
            }                                                               \
            float dot0 = h2sum(d0a) + h2sum(d0b);                           \
            float dot1 = h2sum(d1a) + h2sum(d1b);                           \
            _Pragma("unroll")                                               \
            for (int o = 16; o; o >>= 1) {                                  \
                dot0 += __shfl_xor_sync(0xffffffffu, dot0, o);              \
                dot1 += __shfl_xor_sync(0xffffffffu, dot1, o);              \
            }                                                               \
            const float e0 = __expf(dot0);                                  \
            const float e1 = __expf(dot1);                                  \
            s += e0 + e1;                                                   \
            ull e02, e12;                                                   \
            PACK2(e02, e0);                                                 \
            PACK2(e12, e1);                                                 \
            _Pragma("unroll")                                               \
            for (int u = 0; u < NU; ++u) {                                  \
                FFMA2(acc[u], e02, p0[u]);                                  \
                FFMA2(acc[u], e12, p1[u]);                                  \
            }                                                               \
        } while (0)

    {
        int r = start;
        int cnt = end - start;
        if (cnt & 1) {                     // odd leading row processed singly
            LOADROW(a0, la0, r);
            PROCROW(a0, la0);
            ++r;
        }
        if (r < end) {
            // even number of rows remain; ping-pong pairs
            LOADROW(a0, la0, r);
            LOADROW(a1, la1, r + 1);
            for (;;) {
                const bool hb = r + 3 < end;
                if (hb) {
                    LOADROW(b0, lb0, r + 2);
                    LOADROW(b1, lb1, r + 3);
                }
                PROCPAIR(a0, la0, a1, la1);
                if (!hb) break;
                const bool ha = r + 5 < end;
                if (ha) {
                    LOADROW(a0, la0, r + 4);
                    LOADROW(a1, la1, r + 5);
                }
                PROCPAIR(b0, lb0, b1, lb1);
                if (!ha) break;
                r += 4;
            }
        }
    }

    ull invS2;
    PACK2(invS2, 1.f / s);
    ull* dst = (ull*)(att_out + (size_t)bag * D);
    #pragma unroll
    for (int u = 0; u < 10; ++u) {
        ull t;
        MUL2(t, acc[u], invS2);
        STG_EL(dst + lane + 32 * u, t, pol_el);
    }
    if (tail) {
        ull t;
        MUL2(t, acc[10], invS2);
        STG_EL(dst + lane + 320, t, pol_el);
    }
}

// ---------------------------------------------------------------------------
// Kernel 2 (reverted to R14 best): logits = att @ rel^T + bias
// 64x64 tile, 128 threads, thread tile 4m x 8n (f32x2), BK=16,
// GMEM->reg prefetch pipeline. att expected L2-resident.
// ---------------------------------------------------------------------------
#define BK 16
#define TST 68   // smem row stride (floats), %4==0 for LDS.128

__global__ __launch_bounds__(128)
void bag_logits_gemm(const float* __restrict__ att,
                     const float* __restrict__ rel,
                     const float* __restrict__ bias,
                     float* __restrict__ out,
                     int num_bags)
{
    __shared__ __align__(16) float As[BK][TST];
    __shared__ __align__(16) float Bs[BK][TST];

    const int tid  = threadIdx.x;
    const int m0   = (tid & 15) * 4;        // 4 consecutive bags per thread
    const int n0   = (tid >> 4) * 8;        // 8 consecutive n per thread
    const int bRow = blockIdx.x * 64;

    const int lc = tid & 15;                // k within chunk
    const int lr = tid >> 4;                // row base (stride 8)

    ull acc[4][4];
    #pragma unroll
    for (int i = 0; i < 4; ++i)
        #pragma unroll
        for (int j = 0; j < 4; ++j) acc[i][j] = 0ull;

    float aReg[8], bReg[8];

    #define LOADTILE(k0)                                                     \
        do {                                                                 \
            _Pragma("unroll")                                                \
            for (int p = 0; p < 8; ++p) {                                    \
                int r = lr + p * 8;                                          \
                int bag = bRow + r, k = (k0) + lc;                           \
                aReg[p] = (bag < num_bags && k < D)                          \
                              ? att[(size_t)bag * D + k] : 0.f;              \
                bReg[p] = (r < R && k < D)                                   \
                              ? rel[(size_t)r * D + k] : 0.f;                \
            }                                                                \
        } while (0)

    const int nChunks = (D + BK - 1) / BK;  // 44
    LOADTILE(0);

    for (int t = 0; t < nChunks; ++t) {
        #pragma unroll
        for (int p = 0; p < 8; ++p) {
            As[lc][lr + p * 8] = aReg[p];
            Bs[lc][lr + p * 8] = bReg[p];
        }
        __syncthreads();

        if (t + 1 < nChunks) LOADTILE((t + 1) * BK);

        #pragma unroll
        for (int kk = 0; kk < BK; ++kk) {
            float4 av = *(const float4*)&As[kk][m0];
            ull a0d, a1d, a2d, a3d;
            PACK2(a0d, av.x);
            PACK2(a1d, av.y);
            PACK2(a2d, av.z);
            PACK2(a3d, av.w);
            const ull* bp = (const ull*)&Bs[kk][n0];
            ull b01 = bp[0], b23 = bp[1], b45 = bp[2], b67 = bp[3];
            FFMA2(acc[0][0], a0d, b01); FFMA2(acc[0][1], a0d, b23);
            FFMA2(acc[0][2], a0d, b45); FFMA2(acc[0][3], a0d, b67);
            FFMA2(acc[1][0], a1d, b01); FFMA2(acc[1][1], a1d, b23);
            FFMA2(acc[1][2], a1d, b45); FFMA2(acc[1][3], a1d, b67);
            FFMA2(acc[2][0], a2d, b01); FFMA2(acc[2][1], a2d, b23);
            FFMA2(acc[2][2], a2d, b45); FFMA2(acc[2][3], a2d, b67);
            FFMA2(acc[3][0], a3d, b01); FFMA2(acc[3][1], a3d, b23);
            FFMA2(acc[3][2], a3d, b45); FFMA2(acc[3][3], a3d, b67);
        }
        __syncthreads();
    }

    #pragma unroll
    for (int mm = 0; mm < 4; ++mm) {
        int bag = bRow + m0 + mm;
        if (bag >= num_bags) continue;
        #pragma unroll
        for (int j = 0; j < 4; ++j) {
            union { ull u; float2 f; } v;
            v.u = acc[mm][j];
            int n = n0 + 2 * j;
            if (n < R)     out[(size_t)bag * R + n]     = v.f.x + bias[n];
            if (n + 1 < R) out[(size_t)bag * R + n + 1] = v.f.y + bias[n + 1];
        }
    }
}

extern "C" void kernel_launch(void* const* d_in, const int* in_sizes, int n_in,
                              void* d_out, int out_size)
{
    const float* repre  = (const float*)d_in[0];
    const float* rel    = (const float*)d_in[1];
    const float* bias   = (const float*)d_in[2];
    const int*   scope  = (const int*)d_in[3];
    const int*   labels = (const int*)d_in[4];
    float* out = (float*)d_out;

    const int num_bags = in_sizes[3] / 2;

    float* att;
    cudaGetSymbolAddress((void**)&att, g_att);

    bag_att_kernel<<<num_bags, 32>>>(repre, rel, scope, labels, att);

    int grid2 = (num_bags + 63) / 64;
    bag_logits_gemm<<<grid2, 128>>>(att, rel, bias, out, num_bags);
}